// round 11
// baseline (speedup 1.0000x reference)
#include <cuda_runtime.h>

#define BATCH 64
#define TT    200
#define NUM_C 2000
#define DIM   128
#define MM    50
#define NX    4000        // distinct x = skill + 2000*answer

// ---------------- scratch (device globals; no allocation allowed) ----------
// g_w: per-skill softmax weights, repacked as 8 groups x stride 8:
//   original m = mg*7 + i  ->  slot mg*8 + i   (i<7; slot i=7 unused pad)
// so one thread's 7 values = two aligned LDG.128.
__device__ __align__(16) float g_w[NUM_C * 64];
__device__ __align__(16) float g_ea[NX * 256];        // [x][0:128]=e, [128:256]=a
__device__ __align__(16) float g_kf[NUM_C * DIM];     // k-part of f GEMM + f_b folded
__device__ __align__(16) float g_reads[BATCH * TT * DIM];
__device__ __align__(16) float g_fWat[DIM * DIM];     // [k][i] = f_W[i*256 + k] (reads part)

__device__ __forceinline__ float sigmoidf_(float x) { return 1.f / (1.f + __expf(-x)); }

// =====================================================================
// w table: softmax(k_emb[c] · Mk^T) over 50 slots; 125 CTAs
// writes the group-padded layout described above.
// =====================================================================
__global__ void k_wtable(const float* __restrict__ k_emb, const float* __restrict__ Mk) {
    __shared__ float mksh[DIM * 65];   // padded transpose, conflict-free
    __shared__ float ksh[4 * DIM];
    __shared__ float gmax[8], gsum[8];
    int tid = threadIdx.x;
    int c0 = blockIdx.x * 16;
    int m = tid & 63, cg = tid >> 6, wh = (tid >> 5) & 1;
    for (int i = tid; i < MM * DIM; i += 256) {
        int mm = i >> 7, j = i & 127;
        mksh[j * 65 + mm] = Mk[i];
    }
    for (int cl = 0; cl < 16; cl += 4) {
        int c = c0 + cl + cg;
        __syncthreads();
        for (int j = tid; j < 4 * DIM; j += 256)
            ksh[j] = k_emb[(c0 + cl + (j >> 7)) * DIM + (j & 127)];
        __syncthreads();
        float acc = 0.f;
        if (m < MM) {
            #pragma unroll 8
            for (int j = 0; j < DIM; j++) acc = fmaf(ksh[cg * DIM + j], mksh[j * 65 + m], acc);
        }
        float lg = (m < MM) ? acc : -1e30f;
        float mx = lg;
        #pragma unroll
        for (int off = 16; off; off >>= 1) mx = fmaxf(mx, __shfl_xor_sync(~0u, mx, off));
        if ((tid & 31) == 0) gmax[cg * 2 + wh] = mx;
        __syncthreads();
        mx = fmaxf(gmax[cg * 2], gmax[cg * 2 + 1]);
        float ex = (m < MM) ? __expf(lg - mx) : 0.f;
        float sv = ex;
        #pragma unroll
        for (int off = 16; off; off >>= 1) sv += __shfl_xor_sync(~0u, sv, off);
        if ((tid & 31) == 0) gsum[cg * 2 + wh] = sv;
        __syncthreads();
        float s = gsum[cg * 2] + gsum[cg * 2 + 1];
        if (m < 56) g_w[c * 64 + (m / 7) * 8 + (m % 7)] = ex / s;   // 0 for m>=50
    }
}

// =====================================================================
// e/a table: 4000 x 256 GEMM (K=128) + activations; 125 CTAs; plain FMA
// =====================================================================
__global__ void k_ea(const float* __restrict__ v_emb, const float* __restrict__ e_b,
                     const float* __restrict__ a_b,
                     const float* __restrict__ e_W, const float* __restrict__ a_W) {
    __shared__ float Xs[32 * DIM];
    __shared__ __align__(16) float Ws[16 * 260];
    int row0 = blockIdx.x * 32;
    int tid = threadIdx.x;
    int tx = tid & 31, ty = tid >> 5;       // col = tx*8, rows ty*4..+3
    for (int i = tid; i < 32 * DIM; i += 256) Xs[i] = v_emb[row0 * DIM + i];
    float acc[4][8];
    #pragma unroll
    for (int u = 0; u < 4; u++)
        #pragma unroll
        for (int v = 0; v < 8; v++) acc[u][v] = 0.f;
    for (int kc = 0; kc < DIM; kc += 16) {
        __syncthreads();
        for (int i = tid; i < 16 * 256; i += 256) {
            int kk = i & 15, c = i >> 4;    // coalesced read, transposed write
            float v = (c < DIM) ? e_W[c * DIM + kc + kk] : a_W[(c - DIM) * DIM + kc + kk];
            Ws[kk * 260 + c] = v;
        }
        __syncthreads();
        #pragma unroll
        for (int kk = 0; kk < 16; kk++) {
            float xv[4];
            #pragma unroll
            for (int u = 0; u < 4; u++) xv[u] = Xs[(ty * 4 + u) * DIM + kc + kk];
            float4 w0 = *(const float4*)&Ws[kk * 260 + tx * 8];
            float4 w1 = *(const float4*)&Ws[kk * 260 + tx * 8 + 4];
            #pragma unroll
            for (int u = 0; u < 4; u++) {
                acc[u][0] = fmaf(xv[u], w0.x, acc[u][0]);
                acc[u][1] = fmaf(xv[u], w0.y, acc[u][1]);
                acc[u][2] = fmaf(xv[u], w0.z, acc[u][2]);
                acc[u][3] = fmaf(xv[u], w0.w, acc[u][3]);
                acc[u][4] = fmaf(xv[u], w1.x, acc[u][4]);
                acc[u][5] = fmaf(xv[u], w1.y, acc[u][5]);
                acc[u][6] = fmaf(xv[u], w1.z, acc[u][6]);
                acc[u][7] = fmaf(xv[u], w1.w, acc[u][7]);
            }
        }
    }
    int col = tx * 8;
    float barr[8];
    #pragma unroll
    for (int v = 0; v < 8; v++) {
        int cc = col + v;
        barr[v] = (cc < DIM) ? e_b[cc] : a_b[cc - DIM];
    }
    #pragma unroll
    for (int u = 0; u < 4; u++) {
        float o[8];
        #pragma unroll
        for (int v = 0; v < 8; v++) {
            float z = acc[u][v] + barr[v];
            o[v] = (col + v < DIM) ? sigmoidf_(z) : tanhf(z);
        }
        int r = row0 + ty * 4 + u;
        *(float4*)&g_ea[r * 256 + col]     = make_float4(o[0], o[1], o[2], o[3]);
        *(float4*)&g_ea[r * 256 + col + 4] = make_float4(o[4], o[5], o[6], o[7]);
    }
}

// =====================================================================
// kf table (63 CTAs) + f_W(reads-half) transpose (8 CTAs); plain FMA
// =====================================================================
__global__ void k_kfT(const float* __restrict__ k_emb, const float* __restrict__ f_b,
                      const float* __restrict__ f_W) {
    __shared__ float Xs[32 * DIM];
    __shared__ __align__(16) float Ws[16 * 132];
    int bid = blockIdx.x;
    int tid = threadIdx.x;
    if (bid >= 63) {
        int base = (bid - 63) * 2048;
        #pragma unroll
        for (int j = 0; j < 8; j++) {
            int idx = base + j * 256 + tid;
            int k = idx >> 7, ii = idx & 127;
            g_fWat[idx] = f_W[ii * 256 + k];
        }
        return;
    }
    int row0 = bid * 32;
    for (int i = tid; i < 32 * DIM; i += 256) {
        int rr = i >> 7;
        Xs[i] = (row0 + rr < NUM_C) ? k_emb[row0 * DIM + i] : 0.f;
    }
    int tx = tid & 31, ty = tid >> 5;      // col = tx*4
    float acc[4][4];
    #pragma unroll
    for (int u = 0; u < 4; u++)
        #pragma unroll
        for (int v = 0; v < 4; v++) acc[u][v] = 0.f;
    for (int kc = 0; kc < DIM; kc += 16) {
        __syncthreads();
        for (int i = tid; i < 16 * DIM; i += 256) {
            int kk = i & 15, col = i >> 4;
            Ws[kk * 132 + col] = f_W[col * 256 + 128 + kc + kk];
        }
        __syncthreads();
        #pragma unroll
        for (int kk = 0; kk < 16; kk++) {
            float4 w0 = *(const float4*)&Ws[kk * 132 + tx * 4];
            #pragma unroll
            for (int u = 0; u < 4; u++) {
                float x = Xs[(ty * 4 + u) * DIM + kc + kk];
                acc[u][0] = fmaf(x, w0.x, acc[u][0]);
                acc[u][1] = fmaf(x, w0.y, acc[u][1]);
                acc[u][2] = fmaf(x, w0.z, acc[u][2]);
                acc[u][3] = fmaf(x, w0.w, acc[u][3]);
            }
        }
    }
    int col = tx * 4;
    float b0 = f_b[col], b1 = f_b[col + 1], b2 = f_b[col + 2], b3 = f_b[col + 3];
    #pragma unroll
    for (int u = 0; u < 4; u++) {
        int r = row0 + ty * 4 + u;
        if (r < NUM_C)
            *(float4*)&g_kf[r * DIM + col] =
                make_float4(acc[u][0] + b0, acc[u][1] + b1, acc[u][2] + b2, acc[u][3] + b3);
    }
}

// =====================================================================
// Scan, BARRIER-FREE: 512 CTAs = 64 b x 8 d-slices of 16, 128 threads.
// Each thread gathers its own w (2x LDG.128 from group-padded g_w) and
// e/a (2x LDG.32) directly into a 4-deep register rotation; no smem
// staging, no __syncthreads in the main loop. Warps fully autonomous.
//   lane = mg*4 + dq  (mg in 0..7 = m-group of 7, dq in 0..3)
//   dd   = dbase + wid*4 + dq  (global d)
// Reduction over 8 m-groups = 3 in-warp shfl_xor (4, 8, 16).
// =====================================================================
__global__ __launch_bounds__(128) void k_scan(const int* __restrict__ skill,
                                              const int* __restrict__ answer,
                                              const float* __restrict__ Mv0) {
    __shared__ int s_sk[TT], s_x[TT];
    int b = blockIdx.x >> 3;
    int dbase = (blockIdx.x & 7) * 16;
    int tid = threadIdx.x;
    int wid = tid >> 5, lane = tid & 31;
    int mg = lane >> 2;
    int dd = dbase + wid * 4 + (lane & 3);          // global d, 0..127

    for (int t = tid; t < TT; t += 128) {
        int s = skill[b * TT + t];
        int aa = answer[b * TT + t];
        if (aa > 1) aa = 1;
        s_sk[t] = s;
        s_x[t] = s + NUM_C * aa;
    }

    float mv[7];
    #pragma unroll
    for (int i = 0; i < 7; i++) {
        int m = mg * 7 + i;
        mv[i] = (m < MM) ? Mv0[m * DIM + dd] : 0.f;
    }
    __syncthreads();   // s_sk/s_x visible; ONLY barrier in this kernel

    // 4-deep register rotation of prefetched operands
    float4 wA[4], wB[4];
    float eb[4], ab[4];
    #pragma unroll
    for (int q = 0; q < 4; q++) {
        const float4* wp = (const float4*)&g_w[s_sk[q] * 64 + mg * 8];
        wA[q] = wp[0];
        wB[q] = wp[1];
        eb[q] = g_ea[s_x[q] * 256 + dd];
        ab[q] = g_ea[s_x[q] * 256 + 128 + dd];
    }

    int outbase = b * TT * DIM + dd;

    for (int t0 = 0; t0 < TT; t0 += 4) {
        #pragma unroll
        for (int q = 0; q < 4; q++) {
            int t = t0 + q;
            float e = eb[q], a = ab[q];
            float w0 = wA[q].x, w1 = wA[q].y, w2 = wA[q].z, w3 = wA[q].w;
            float w4 = wB[q].x, w5 = wB[q].y, w6 = wB[q].z;
            float acc;
            acc = w0 * mv[0];                 mv[0] = fmaf(w0, fmaf(-e, mv[0], a), mv[0]);
            acc = fmaf(w1, mv[1], acc);       mv[1] = fmaf(w1, fmaf(-e, mv[1], a), mv[1]);
            acc = fmaf(w2, mv[2], acc);       mv[2] = fmaf(w2, fmaf(-e, mv[2], a), mv[2]);
            acc = fmaf(w3, mv[3], acc);       mv[3] = fmaf(w3, fmaf(-e, mv[3], a), mv[3]);
            acc = fmaf(w4, mv[4], acc);       mv[4] = fmaf(w4, fmaf(-e, mv[4], a), mv[4]);
            acc = fmaf(w5, mv[5], acc);       mv[5] = fmaf(w5, fmaf(-e, mv[5], a), mv[5]);
            acc = fmaf(w6, mv[6], acc);       mv[6] = fmaf(w6, fmaf(-e, mv[6], a), mv[6]);
            acc += __shfl_xor_sync(~0u, acc, 4);
            acc += __shfl_xor_sync(~0u, acc, 8);
            acc += __shfl_xor_sync(~0u, acc, 16);
            if (lane < 4) g_reads[outbase + t * DIM] = acc;
            // prefetch step t+4 into the slot just consumed
            if (t + 4 < TT) {
                const float4* wp = (const float4*)&g_w[s_sk[t + 4] * 64 + mg * 8];
                wA[q] = wp[0];
                wB[q] = wp[1];
                eb[q] = g_ea[s_x[t + 4] * 256 + dd];
                ab[q] = g_ea[s_x[t + 4] * 256 + 128 + dd];
            }
        }
    }
}

// =====================================================================
// fpred: f = tanh(reads@fWat + kf[skill]); gathered pred. 199 CTAs x 64.
// =====================================================================
__global__ void k_fpred(const int* __restrict__ skill, const float* __restrict__ p_W,
                        const float* __restrict__ p_b, float* __restrict__ out) {
    __shared__ float Xs[64][130];                 // reads tile; later reused for f
    __shared__ __align__(16) float Ws[16][DIM];
    __shared__ int s_kf[64], s_nx[64], roff[64];
    int row0 = blockIdx.x * 64;
    int tid = threadIdx.x;
    if (tid < 64) {
        int r = row0 + tid;
        int b = r / 199;
        int t = r - b * 199;
        s_kf[tid] = skill[b * TT + t];
        s_nx[tid] = skill[b * TT + t + 1];
        roff[tid] = (b * TT + t) * DIM;
    }
    __syncthreads();
    for (int i = tid; i < 64 * DIM; i += 256) {
        int rr = i >> 7, k = i & 127;
        Xs[rr][k] = g_reads[roff[rr] + k];
    }
    int tx = tid & 15, ty = tid >> 4;   // col = tx*8, rows = ty*4..
    float acc[4][8];
    #pragma unroll
    for (int u = 0; u < 4; u++)
        #pragma unroll
        for (int v = 0; v < 8; v++) acc[u][v] = 0.f;
    for (int kc = 0; kc < DIM; kc += 16) {
        __syncthreads();
        for (int i = tid; i < 16 * DIM; i += 256)
            Ws[i >> 7][i & 127] = g_fWat[(kc + (i >> 7)) * DIM + (i & 127)];
        __syncthreads();
        #pragma unroll
        for (int kk = 0; kk < 16; kk++) {
            float xv[4];
            #pragma unroll
            for (int u = 0; u < 4; u++) xv[u] = Xs[ty * 4 + u][kc + kk];
            float4 w0 = *(const float4*)&Ws[kk][tx * 8];
            float4 w1 = *(const float4*)&Ws[kk][tx * 8 + 4];
            #pragma unroll
            for (int u = 0; u < 4; u++) {
                acc[u][0] = fmaf(xv[u], w0.x, acc[u][0]);
                acc[u][1] = fmaf(xv[u], w0.y, acc[u][1]);
                acc[u][2] = fmaf(xv[u], w0.z, acc[u][2]);
                acc[u][3] = fmaf(xv[u], w0.w, acc[u][3]);
                acc[u][4] = fmaf(xv[u], w1.x, acc[u][4]);
                acc[u][5] = fmaf(xv[u], w1.y, acc[u][5]);
                acc[u][6] = fmaf(xv[u], w1.z, acc[u][6]);
                acc[u][7] = fmaf(xv[u], w1.w, acc[u][7]);
            }
        }
    }
    __syncthreads();   // everyone done reading Xs -> overwrite with f
    int col = tx * 8;
    #pragma unroll
    for (int u = 0; u < 4; u++) {
        int row = ty * 4 + u;
        int sc = s_kf[row];
        float4 k0 = *(const float4*)&g_kf[sc * DIM + col];
        float4 k1 = *(const float4*)&g_kf[sc * DIM + col + 4];
        Xs[row][col + 0] = tanhf(acc[u][0] + k0.x);
        Xs[row][col + 1] = tanhf(acc[u][1] + k0.y);
        Xs[row][col + 2] = tanhf(acc[u][2] + k0.z);
        Xs[row][col + 3] = tanhf(acc[u][3] + k0.w);
        Xs[row][col + 4] = tanhf(acc[u][4] + k1.x);
        Xs[row][col + 5] = tanhf(acc[u][5] + k1.y);
        Xs[row][col + 6] = tanhf(acc[u][6] + k1.z);
        Xs[row][col + 7] = tanhf(acc[u][7] + k1.w);
    }
    __syncthreads();
    int wid = tid >> 5, lane = tid & 31;
    for (int rr = wid * 8; rr < wid * 8 + 8; rr++) {
        int ns = s_nx[rr];
        int idx = (ns < NUM_C) ? ns : (NUM_C - 1);
        const float* pw = p_W + idx * DIM;
        float a = 0.f;
        #pragma unroll
        for (int q = 0; q < 4; q++) a = fmaf(Xs[rr][lane + 32 * q], pw[lane + 32 * q], a);
        #pragma unroll
        for (int off = 16; off; off >>= 1) a += __shfl_xor_sync(~0u, a, off);
        if (lane == 0) {
            float pr = sigmoidf_(a + p_b[idx]);
            out[row0 + rr] = (ns < NUM_C) ? pr : 0.f;
        }
    }
}

// ---------------- launch: forked-capture stream graph ----------------------
extern "C" void kernel_launch(void* const* d_in, const int* in_sizes, int n_in,
                              void* d_out, int out_size) {
    const int*   skill  = (const int*)d_in[0];
    const int*   answer = (const int*)d_in[1];
    const float* k_emb  = (const float*)d_in[2];
    const float* v_emb  = (const float*)d_in[3];
    const float* Mk     = (const float*)d_in[4];
    const float* Mv0    = (const float*)d_in[5];
    const float* f_W    = (const float*)d_in[6];
    const float* f_b    = (const float*)d_in[7];
    const float* p_W    = (const float*)d_in[8];
    const float* p_b    = (const float*)d_in[9];
    const float* e_W    = (const float*)d_in[10];
    const float* e_b    = (const float*)d_in[11];
    const float* a_W    = (const float*)d_in[12];
    const float* a_b    = (const float*)d_in[13];
    float* out = (float*)d_out;

    static cudaStream_t sA = nullptr, sB = nullptr, sC = nullptr;
    static cudaEvent_t evR = nullptr, evA = nullptr, evB = nullptr, evC = nullptr;
    if (!sA) {   // first call = correctness run (not captured): safe to create
        cudaStreamCreateWithFlags(&sA, cudaStreamNonBlocking);
        cudaStreamCreateWithFlags(&sB, cudaStreamNonBlocking);
        cudaStreamCreateWithFlags(&sC, cudaStreamNonBlocking);
        cudaEventCreateWithFlags(&evR, cudaEventDisableTiming);
        cudaEventCreateWithFlags(&evA, cudaEventDisableTiming);
        cudaEventCreateWithFlags(&evB, cudaEventDisableTiming);
        cudaEventCreateWithFlags(&evC, cudaEventDisableTiming);
    }

    cudaEventRecord(evR, 0);
    cudaStreamWaitEvent(sA, evR, 0);
    cudaStreamWaitEvent(sB, evR, 0);
    cudaStreamWaitEvent(sC, evR, 0);

    k_wtable<<<125, 256, 0, sA>>>(k_emb, Mk);
    k_ea    <<<125, 256, 0, sB>>>(v_emb, e_b, a_b, e_W, a_W);
    k_kfT   <<<71, 256, 0, sC>>>(k_emb, f_b, f_W);      // overlaps scan

    cudaEventRecord(evA, sA);
    cudaEventRecord(evB, sB);
    cudaEventRecord(evC, sC);

    cudaStreamWaitEvent(0, evA, 0);
    cudaStreamWaitEvent(0, evB, 0);
    k_scan<<<512, 128>>>(skill, answer, Mv0);

    cudaStreamWaitEvent(0, evC, 0);
    k_fpred<<<199, 256>>>(skill, p_W, p_b, out);
}

// round 12
// speedup vs baseline: 1.0293x; 1.0293x over previous
#include <cuda_runtime.h>

#define BATCH 64
#define TT    200
#define NUM_C 2000
#define DIM   128
#define MM    50
#define MP    56          // M padded; rows 50..55 have w=0 (inert)
#define NX    4000        // distinct x = skill + 2000*answer

// ---------------- scratch (device globals; no allocation allowed) ----------
__device__ __align__(16) float g_w[NUM_C * MP];       // softmax(k·Mk^T) per skill id
__device__ __align__(16) float g_ea[NX * 256];        // [x][0:128]=e, [128:256]=a
__device__ __align__(16) float g_kf[NUM_C * DIM];     // k-part of f GEMM + f_b folded
__device__ __align__(16) float g_reads[BATCH * TT * DIM];
__device__ __align__(16) float g_fWat[DIM * DIM];     // [k][i] = f_W[i*256 + k] (reads part)

__device__ __forceinline__ float sigmoidf_(float x) { return 1.f / (1.f + __expf(-x)); }

// =====================================================================
// w table: softmax(k_emb[c] · Mk^T) over 50 slots; 125 CTAs
// =====================================================================
__global__ void k_wtable(const float* __restrict__ k_emb, const float* __restrict__ Mk) {
    __shared__ float mksh[DIM * 65];   // padded transpose, conflict-free
    __shared__ float ksh[4 * DIM];
    __shared__ float gmax[8], gsum[8];
    int tid = threadIdx.x;
    int c0 = blockIdx.x * 16;
    int m = tid & 63, cg = tid >> 6, wh = (tid >> 5) & 1;
    for (int i = tid; i < MM * DIM; i += 256) {
        int mm = i >> 7, j = i & 127;
        mksh[j * 65 + mm] = Mk[i];
    }
    for (int cl = 0; cl < 16; cl += 4) {
        int c = c0 + cl + cg;
        __syncthreads();
        for (int j = tid; j < 4 * DIM; j += 256)
            ksh[j] = k_emb[(c0 + cl + (j >> 7)) * DIM + (j & 127)];
        __syncthreads();
        float acc = 0.f;
        if (m < MM) {
            #pragma unroll 8
            for (int j = 0; j < DIM; j++) acc = fmaf(ksh[cg * DIM + j], mksh[j * 65 + m], acc);
        }
        float lg = (m < MM) ? acc : -1e30f;
        float mx = lg;
        #pragma unroll
        for (int off = 16; off; off >>= 1) mx = fmaxf(mx, __shfl_xor_sync(~0u, mx, off));
        if ((tid & 31) == 0) gmax[cg * 2 + wh] = mx;
        __syncthreads();
        mx = fmaxf(gmax[cg * 2], gmax[cg * 2 + 1]);
        float ex = (m < MM) ? __expf(lg - mx) : 0.f;
        float sv = ex;
        #pragma unroll
        for (int off = 16; off; off >>= 1) sv += __shfl_xor_sync(~0u, sv, off);
        if ((tid & 31) == 0) gsum[cg * 2 + wh] = sv;
        __syncthreads();
        float s = gsum[cg * 2] + gsum[cg * 2 + 1];
        if (m < MP) g_w[c * MP + m] = ex / s;
    }
}

// =====================================================================
// e/a table: 4000 x 256 GEMM (K=128) + activations; 125 CTAs; plain FMA
// =====================================================================
__global__ void k_ea(const float* __restrict__ v_emb, const float* __restrict__ e_b,
                     const float* __restrict__ a_b,
                     const float* __restrict__ e_W, const float* __restrict__ a_W) {
    __shared__ float Xs[32 * DIM];
    __shared__ __align__(16) float Ws[16 * 260];
    int row0 = blockIdx.x * 32;
    int tid = threadIdx.x;
    int tx = tid & 31, ty = tid >> 5;       // col = tx*8, rows ty*4..+3
    for (int i = tid; i < 32 * DIM; i += 256) Xs[i] = v_emb[row0 * DIM + i];
    float acc[4][8];
    #pragma unroll
    for (int u = 0; u < 4; u++)
        #pragma unroll
        for (int v = 0; v < 8; v++) acc[u][v] = 0.f;
    for (int kc = 0; kc < DIM; kc += 16) {
        __syncthreads();
        for (int i = tid; i < 16 * 256; i += 256) {
            int kk = i & 15, c = i >> 4;    // coalesced read, transposed write
            float v = (c < DIM) ? e_W[c * DIM + kc + kk] : a_W[(c - DIM) * DIM + kc + kk];
            Ws[kk * 260 + c] = v;
        }
        __syncthreads();
        #pragma unroll
        for (int kk = 0; kk < 16; kk++) {
            float xv[4];
            #pragma unroll
            for (int u = 0; u < 4; u++) xv[u] = Xs[(ty * 4 + u) * DIM + kc + kk];
            float4 w0 = *(const float4*)&Ws[kk * 260 + tx * 8];
            float4 w1 = *(const float4*)&Ws[kk * 260 + tx * 8 + 4];
            #pragma unroll
            for (int u = 0; u < 4; u++) {
                acc[u][0] = fmaf(xv[u], w0.x, acc[u][0]);
                acc[u][1] = fmaf(xv[u], w0.y, acc[u][1]);
                acc[u][2] = fmaf(xv[u], w0.z, acc[u][2]);
                acc[u][3] = fmaf(xv[u], w0.w, acc[u][3]);
                acc[u][4] = fmaf(xv[u], w1.x, acc[u][4]);
                acc[u][5] = fmaf(xv[u], w1.y, acc[u][5]);
                acc[u][6] = fmaf(xv[u], w1.z, acc[u][6]);
                acc[u][7] = fmaf(xv[u], w1.w, acc[u][7]);
            }
        }
    }
    int col = tx * 8;
    float barr[8];
    #pragma unroll
    for (int v = 0; v < 8; v++) {
        int cc = col + v;
        barr[v] = (cc < DIM) ? e_b[cc] : a_b[cc - DIM];
    }
    #pragma unroll
    for (int u = 0; u < 4; u++) {
        float o[8];
        #pragma unroll
        for (int v = 0; v < 8; v++) {
            float z = acc[u][v] + barr[v];
            o[v] = (col + v < DIM) ? sigmoidf_(z) : tanhf(z);
        }
        int r = row0 + ty * 4 + u;
        *(float4*)&g_ea[r * 256 + col]     = make_float4(o[0], o[1], o[2], o[3]);
        *(float4*)&g_ea[r * 256 + col + 4] = make_float4(o[4], o[5], o[6], o[7]);
    }
}

// =====================================================================
// kf table (63 CTAs) + f_W(reads-half) transpose (8 CTAs); plain FMA
// =====================================================================
__global__ void k_kfT(const float* __restrict__ k_emb, const float* __restrict__ f_b,
                      const float* __restrict__ f_W) {
    __shared__ float Xs[32 * DIM];
    __shared__ __align__(16) float Ws[16 * 132];
    int bid = blockIdx.x;
    int tid = threadIdx.x;
    if (bid >= 63) {
        int base = (bid - 63) * 2048;
        #pragma unroll
        for (int j = 0; j < 8; j++) {
            int idx = base + j * 256 + tid;
            int k = idx >> 7, ii = idx & 127;
            g_fWat[idx] = f_W[ii * 256 + k];
        }
        return;
    }
    int row0 = bid * 32;
    for (int i = tid; i < 32 * DIM; i += 256) {
        int rr = i >> 7;
        Xs[i] = (row0 + rr < NUM_C) ? k_emb[row0 * DIM + i] : 0.f;
    }
    int tx = tid & 31, ty = tid >> 5;      // col = tx*4
    float acc[4][4];
    #pragma unroll
    for (int u = 0; u < 4; u++)
        #pragma unroll
        for (int v = 0; v < 4; v++) acc[u][v] = 0.f;
    for (int kc = 0; kc < DIM; kc += 16) {
        __syncthreads();
        for (int i = tid; i < 16 * DIM; i += 256) {
            int kk = i & 15, col = i >> 4;
            Ws[kk * 132 + col] = f_W[col * 256 + 128 + kc + kk];
        }
        __syncthreads();
        #pragma unroll
        for (int kk = 0; kk < 16; kk++) {
            float4 w0 = *(const float4*)&Ws[kk * 132 + tx * 4];
            #pragma unroll
            for (int u = 0; u < 4; u++) {
                float x = Xs[(ty * 4 + u) * DIM + kc + kk];
                acc[u][0] = fmaf(x, w0.x, acc[u][0]);
                acc[u][1] = fmaf(x, w0.y, acc[u][1]);
                acc[u][2] = fmaf(x, w0.z, acc[u][2]);
                acc[u][3] = fmaf(x, w0.w, acc[u][3]);
            }
        }
    }
    int col = tx * 4;
    float b0 = f_b[col], b1 = f_b[col + 1], b2 = f_b[col + 2], b3 = f_b[col + 3];
    #pragma unroll
    for (int u = 0; u < 4; u++) {
        int r = row0 + ty * 4 + u;
        if (r < NUM_C)
            *(float4*)&g_kf[r * DIM + col] =
                make_float4(acc[u][0] + b0, acc[u][1] + b1, acc[u][2] + b2, acc[u][3] + b3);
    }
}

// =====================================================================
// Scan: 512 CTAs = 64 b x 8 d-slices of 16, 128 threads (R9 structure)
// + epoch-4 barrier: 8-slot smem ring, ONE __syncthreads per 4 steps.
// Epoch t0: STS steps t0+4..t0+7 (slots disjoint from compute set mod 8),
// LDG steps t0+8..t0+11 into regs, compute steps t0..t0+3, barrier.
//   lane = mg*4 + dq (mg = m-group of 7, dq in 0..3); dd = wid*4+dq.
// Reduction over 8 m-groups = 3 in-warp shfl_xor (4, 8, 16).
// =====================================================================
__global__ __launch_bounds__(128) void k_scan(const int* __restrict__ skill,
                                              const int* __restrict__ answer,
                                              const float* __restrict__ Mv0) {
    __shared__ int s_sk[TT], s_x[TT];
    __shared__ __align__(16) float w_sh[8][MP];
    __shared__ __align__(16) float e_sh[8][16];
    __shared__ __align__(16) float a_sh[8][16];
    int b = blockIdx.x >> 3;
    int dbase = (blockIdx.x & 7) * 16;
    int tid = threadIdx.x;
    int wid = tid >> 5, lane = tid & 31;
    int mg = lane >> 2, dq = lane & 3;
    int dd = wid * 4 + dq;                 // 0..15 within slice

    for (int t = tid; t < TT; t += 128) {
        int s = skill[b * TT + t];
        int aa = answer[b * TT + t];
        if (aa > 1) aa = 1;
        s_sk[t] = s;
        s_x[t] = s + NUM_C * aa;
    }

    float mv[7];
    #pragma unroll
    for (int i = 0; i < 7; i++) {
        int m = mg * 7 + i;
        mv[i] = (m < MM) ? Mv0[m * DIM + dbase + dd] : 0.f;
    }
    __syncthreads();   // s_sk/s_x visible

    // gather roles: tid<56 -> w, [64,80) -> e, [80,96) -> a
    bool isW = tid < MP;
    bool isE = (tid >= 64) && (tid < 80);
    bool isA = (tid >= 80) && (tid < 96);
    bool lp = isW || isE || isA;
    int eoff = isE ? (dbase + (tid - 64)) : (128 + dbase + (tid - 80));

    float pfR[4] = {0.f, 0.f, 0.f, 0.f};
    if (lp) {
        // prologue: fill all 8 slots (steps 0..7), prefetch steps 8..11
        float pre[8];
        #pragma unroll
        for (int r = 0; r < 8; r++)
            pre[r] = isW ? g_w[s_sk[r] * MP + tid] : g_ea[s_x[r] * 256 + eoff];
        #pragma unroll
        for (int r = 0; r < 8; r++) {
            if (isW)      w_sh[r][tid] = pre[r];
            else if (isE) e_sh[r][tid - 64] = pre[r];
            else          a_sh[r][tid - 80] = pre[r];
        }
        #pragma unroll
        for (int j = 0; j < 4; j++)
            pfR[j] = isW ? g_w[s_sk[8 + j] * MP + tid] : g_ea[s_x[8 + j] * 256 + eoff];
    }
    __syncthreads();

    int outbase = (b * TT) * DIM + dbase + dd;

    for (int t0 = 0; t0 < TT; t0 += 4) {
        // ---- STS: steps t0+4..t0+7 (loaded last epoch); skip first epoch
        //      (prologue already filled slots 4..7) ----
        if (t0 > 0 && lp) {
            #pragma unroll
            for (int j = 0; j < 4; j++) {
                int ts = t0 + 4 + j;
                if (ts < TT) {
                    int sl = ts & 7;
                    if (isW)      w_sh[sl][tid] = pfR[j];
                    else if (isE) e_sh[sl][tid - 64] = pfR[j];
                    else          a_sh[sl][tid - 80] = pfR[j];
                }
            }
        }
        // ---- LDG: steps t0+8..t0+11 into pfR ----
        if (lp) {
            #pragma unroll
            for (int j = 0; j < 4; j++) {
                int ts = t0 + 8 + j;
                if (ts < TT)
                    pfR[j] = isW ? g_w[s_sk[ts] * MP + tid] : g_ea[s_x[ts] * 256 + eoff];
            }
        }
        // ---- compute steps t0..t0+3 (slots valid since epoch t0-4) ----
        #pragma unroll
        for (int q = 0; q < 4; q++) {
            int t = t0 + q;
            int sl = t & 7;
            float e = e_sh[sl][dd];
            float a = a_sh[sl][dd];
            float acc = 0.f;
            #pragma unroll
            for (int i = 0; i < 7; i++) {
                float wm = w_sh[sl][mg * 7 + i];
                acc = fmaf(wm, mv[i], acc);                      // PRE-update read
                mv[i] = fmaf(wm, fmaf(-e, mv[i], a), mv[i]);
            }
            acc += __shfl_xor_sync(~0u, acc, 4);
            acc += __shfl_xor_sync(~0u, acc, 8);
            acc += __shfl_xor_sync(~0u, acc, 16);
            if (mg == 0) g_reads[outbase + t * DIM] = acc;
        }
        __syncthreads();
    }
}

// =====================================================================
// fpred: f = tanh(reads@fWat + kf[skill]); gathered pred. 199 CTAs x 64.
// =====================================================================
__global__ void k_fpred(const int* __restrict__ skill, const float* __restrict__ p_W,
                        const float* __restrict__ p_b, float* __restrict__ out) {
    __shared__ float Xs[64][130];                 // reads tile; later reused for f
    __shared__ __align__(16) float Ws[16][DIM];
    __shared__ int s_kf[64], s_nx[64], roff[64];
    int row0 = blockIdx.x * 64;
    int tid = threadIdx.x;
    if (tid < 64) {
        int r = row0 + tid;
        int b = r / 199;
        int t = r - b * 199;
        s_kf[tid] = skill[b * TT + t];
        s_nx[tid] = skill[b * TT + t + 1];
        roff[tid] = (b * TT + t) * DIM;
    }
    __syncthreads();
    for (int i = tid; i < 64 * DIM; i += 256) {
        int rr = i >> 7, k = i & 127;
        Xs[rr][k] = g_reads[roff[rr] + k];
    }
    int tx = tid & 15, ty = tid >> 4;   // col = tx*8, rows = ty*4..
    float acc[4][8];
    #pragma unroll
    for (int u = 0; u < 4; u++)
        #pragma unroll
        for (int v = 0; v < 8; v++) acc[u][v] = 0.f;
    for (int kc = 0; kc < DIM; kc += 16) {
        __syncthreads();
        for (int i = tid; i < 16 * DIM; i += 256)
            Ws[i >> 7][i & 127] = g_fWat[(kc + (i >> 7)) * DIM + (i & 127)];
        __syncthreads();
        #pragma unroll
        for (int kk = 0; kk < 16; kk++) {
            float xv[4];
            #pragma unroll
            for (int u = 0; u < 4; u++) xv[u] = Xs[ty * 4 + u][kc + kk];
            float4 w0 = *(const float4*)&Ws[kk][tx * 8];
            float4 w1 = *(const float4*)&Ws[kk][tx * 8 + 4];
            #pragma unroll
            for (int u = 0; u < 4; u++) {
                acc[u][0] = fmaf(xv[u], w0.x, acc[u][0]);
                acc[u][1] = fmaf(xv[u], w0.y, acc[u][1]);
                acc[u][2] = fmaf(xv[u], w0.z, acc[u][2]);
                acc[u][3] = fmaf(xv[u], w0.w, acc[u][3]);
                acc[u][4] = fmaf(xv[u], w1.x, acc[u][4]);
                acc[u][5] = fmaf(xv[u], w1.y, acc[u][5]);
                acc[u][6] = fmaf(xv[u], w1.z, acc[u][6]);
                acc[u][7] = fmaf(xv[u], w1.w, acc[u][7]);
            }
        }
    }
    __syncthreads();   // everyone done reading Xs -> overwrite with f
    int col = tx * 8;
    #pragma unroll
    for (int u = 0; u < 4; u++) {
        int row = ty * 4 + u;
        int sc = s_kf[row];
        float4 k0 = *(const float4*)&g_kf[sc * DIM + col];
        float4 k1 = *(const float4*)&g_kf[sc * DIM + col + 4];
        Xs[row][col + 0] = tanhf(acc[u][0] + k0.x);
        Xs[row][col + 1] = tanhf(acc[u][1] + k0.y);
        Xs[row][col + 2] = tanhf(acc[u][2] + k0.z);
        Xs[row][col + 3] = tanhf(acc[u][3] + k0.w);
        Xs[row][col + 4] = tanhf(acc[u][4] + k1.x);
        Xs[row][col + 5] = tanhf(acc[u][5] + k1.y);
        Xs[row][col + 6] = tanhf(acc[u][6] + k1.z);
        Xs[row][col + 7] = tanhf(acc[u][7] + k1.w);
    }
    __syncthreads();
    int wid = tid >> 5, lane = tid & 31;
    for (int rr = wid * 8; rr < wid * 8 + 8; rr++) {
        int ns = s_nx[rr];
        int idx = (ns < NUM_C) ? ns : (NUM_C - 1);
        const float* pw = p_W + idx * DIM;
        float a = 0.f;
        #pragma unroll
        for (int q = 0; q < 4; q++) a = fmaf(Xs[rr][lane + 32 * q], pw[lane + 32 * q], a);
        #pragma unroll
        for (int off = 16; off; off >>= 1) a += __shfl_xor_sync(~0u, a, off);
        if (lane == 0) {
            float pr = sigmoidf_(a + p_b[idx]);
            out[row0 + rr] = (ns < NUM_C) ? pr : 0.f;
        }
    }
}

// ---------------- launch: forked-capture stream graph ----------------------
extern "C" void kernel_launch(void* const* d_in, const int* in_sizes, int n_in,
                              void* d_out, int out_size) {
    const int*   skill  = (const int*)d_in[0];
    const int*   answer = (const int*)d_in[1];
    const float* k_emb  = (const float*)d_in[2];
    const float* v_emb  = (const float*)d_in[3];
    const float* Mk     = (const float*)d_in[4];
    const float* Mv0    = (const float*)d_in[5];
    const float* f_W    = (const float*)d_in[6];
    const float* f_b    = (const float*)d_in[7];
    const float* p_W    = (const float*)d_in[8];
    const float* p_b    = (const float*)d_in[9];
    const float* e_W    = (const float*)d_in[10];
    const float* e_b    = (const float*)d_in[11];
    const float* a_W    = (const float*)d_in[12];
    const float* a_b    = (const float*)d_in[13];
    float* out = (float*)d_out;

    static cudaStream_t sA = nullptr, sB = nullptr, sC = nullptr;
    static cudaEvent_t evR = nullptr, evA = nullptr, evB = nullptr, evC = nullptr;
    if (!sA) {   // first call = correctness run (not captured): safe to create
        cudaStreamCreateWithFlags(&sA, cudaStreamNonBlocking);
        cudaStreamCreateWithFlags(&sB, cudaStreamNonBlocking);
        cudaStreamCreateWithFlags(&sC, cudaStreamNonBlocking);
        cudaEventCreateWithFlags(&evR, cudaEventDisableTiming);
        cudaEventCreateWithFlags(&evA, cudaEventDisableTiming);
        cudaEventCreateWithFlags(&evB, cudaEventDisableTiming);
        cudaEventCreateWithFlags(&evC, cudaEventDisableTiming);
    }

    cudaEventRecord(evR, 0);
    cudaStreamWaitEvent(sA, evR, 0);
    cudaStreamWaitEvent(sB, evR, 0);
    cudaStreamWaitEvent(sC, evR, 0);

    k_wtable<<<125, 256, 0, sA>>>(k_emb, Mk);
    k_ea    <<<125, 256, 0, sB>>>(v_emb, e_b, a_b, e_W, a_W);
    k_kfT   <<<71, 256, 0, sC>>>(k_emb, f_b, f_W);      // overlaps scan

    cudaEventRecord(evA, sA);
    cudaEventRecord(evB, sB);
    cudaEventRecord(evC, sC);

    cudaStreamWaitEvent(0, evA, 0);
    cudaStreamWaitEvent(0, evB, 0);
    k_scan<<<512, 128>>>(skill, answer, Mv0);

    cudaStreamWaitEvent(0, evC, 0);
    k_fpred<<<199, 256>>>(skill, p_W, p_b, out);
}

// round 14
// speedup vs baseline: 1.2324x; 1.1973x over previous
#include <cuda_runtime.h>

#define BATCH 64
#define TT    200
#define NUM_C 2000
#define DIM   128
#define MM    50
#define MP    56          // M padded; rows 50..55 have w=0 (inert)
#define NX    4000        // distinct x = skill + 2000*answer

// ---------------- scratch (device globals; no allocation allowed) ----------
__device__ __align__(16) float g_w[NUM_C * MP];       // softmax(k·Mk^T) per skill id
__device__ __align__(16) float g_ea[NX * 256];        // [x][0:128]=e, [128:256]=a
__device__ __align__(16) float g_kf[NUM_C * DIM];     // k-part of f GEMM + f_b folded
__device__ __align__(16) float g_reads[BATCH * TT * DIM];
__device__ __align__(16) float g_fWat[DIM * DIM];     // [k][i] = f_W[i*256 + k] (reads part)

__device__ __forceinline__ float sigmoidf_(float x) { return 1.f / (1.f + __expf(-x)); }

// =====================================================================
// w table: softmax(k_emb[c] · Mk^T) over 50 slots; 125 CTAs
// =====================================================================
__global__ void k_wtable(const float* __restrict__ k_emb, const float* __restrict__ Mk) {
    __shared__ float mksh[DIM * 65];   // padded transpose, conflict-free
    __shared__ float ksh[4 * DIM];
    __shared__ float gmax[8], gsum[8];
    int tid = threadIdx.x;
    int c0 = blockIdx.x * 16;
    int m = tid & 63, cg = tid >> 6, wh = (tid >> 5) & 1;
    for (int i = tid; i < MM * DIM; i += 256) {
        int mm = i >> 7, j = i & 127;
        mksh[j * 65 + mm] = Mk[i];
    }
    for (int cl = 0; cl < 16; cl += 4) {
        int c = c0 + cl + cg;
        __syncthreads();
        for (int j = tid; j < 4 * DIM; j += 256)
            ksh[j] = k_emb[(c0 + cl + (j >> 7)) * DIM + (j & 127)];
        __syncthreads();
        float acc = 0.f;
        if (m < MM) {
            #pragma unroll 8
            for (int j = 0; j < DIM; j++) acc = fmaf(ksh[cg * DIM + j], mksh[j * 65 + m], acc);
        }
        float lg = (m < MM) ? acc : -1e30f;
        float mx = lg;
        #pragma unroll
        for (int off = 16; off; off >>= 1) mx = fmaxf(mx, __shfl_xor_sync(~0u, mx, off));
        if ((tid & 31) == 0) gmax[cg * 2 + wh] = mx;
        __syncthreads();
        mx = fmaxf(gmax[cg * 2], gmax[cg * 2 + 1]);
        float ex = (m < MM) ? __expf(lg - mx) : 0.f;
        float sv = ex;
        #pragma unroll
        for (int off = 16; off; off >>= 1) sv += __shfl_xor_sync(~0u, sv, off);
        if ((tid & 31) == 0) gsum[cg * 2 + wh] = sv;
        __syncthreads();
        float s = gsum[cg * 2] + gsum[cg * 2 + 1];
        if (m < MP) g_w[c * MP + m] = ex / s;
    }
}

// =====================================================================
// e/a table: 4000 x 256 GEMM (K=128) + activations; 125 CTAs; plain FMA
// =====================================================================
__global__ void k_ea(const float* __restrict__ v_emb, const float* __restrict__ e_b,
                     const float* __restrict__ a_b,
                     const float* __restrict__ e_W, const float* __restrict__ a_W) {
    __shared__ float Xs[32 * DIM];
    __shared__ __align__(16) float Ws[16 * 260];
    int row0 = blockIdx.x * 32;
    int tid = threadIdx.x;
    int tx = tid & 31, ty = tid >> 5;       // col = tx*8, rows ty*4..+3
    for (int i = tid; i < 32 * DIM; i += 256) Xs[i] = v_emb[row0 * DIM + i];
    float acc[4][8];
    #pragma unroll
    for (int u = 0; u < 4; u++)
        #pragma unroll
        for (int v = 0; v < 8; v++) acc[u][v] = 0.f;
    for (int kc = 0; kc < DIM; kc += 16) {
        __syncthreads();
        for (int i = tid; i < 16 * 256; i += 256) {
            int kk = i & 15, c = i >> 4;    // coalesced read, transposed write
            float v = (c < DIM) ? e_W[c * DIM + kc + kk] : a_W[(c - DIM) * DIM + kc + kk];
            Ws[kk * 260 + c] = v;
        }
        __syncthreads();
        #pragma unroll
        for (int kk = 0; kk < 16; kk++) {
            float xv[4];
            #pragma unroll
            for (int u = 0; u < 4; u++) xv[u] = Xs[(ty * 4 + u) * DIM + kc + kk];
            float4 w0 = *(const float4*)&Ws[kk * 260 + tx * 8];
            float4 w1 = *(const float4*)&Ws[kk * 260 + tx * 8 + 4];
            #pragma unroll
            for (int u = 0; u < 4; u++) {
                acc[u][0] = fmaf(xv[u], w0.x, acc[u][0]);
                acc[u][1] = fmaf(xv[u], w0.y, acc[u][1]);
                acc[u][2] = fmaf(xv[u], w0.z, acc[u][2]);
                acc[u][3] = fmaf(xv[u], w0.w, acc[u][3]);
                acc[u][4] = fmaf(xv[u], w1.x, acc[u][4]);
                acc[u][5] = fmaf(xv[u], w1.y, acc[u][5]);
                acc[u][6] = fmaf(xv[u], w1.z, acc[u][6]);
                acc[u][7] = fmaf(xv[u], w1.w, acc[u][7]);
            }
        }
    }
    int col = tx * 8;
    float barr[8];
    #pragma unroll
    for (int v = 0; v < 8; v++) {
        int cc = col + v;
        barr[v] = (cc < DIM) ? e_b[cc] : a_b[cc - DIM];
    }
    #pragma unroll
    for (int u = 0; u < 4; u++) {
        float o[8];
        #pragma unroll
        for (int v = 0; v < 8; v++) {
            float z = acc[u][v] + barr[v];
            o[v] = (col + v < DIM) ? sigmoidf_(z) : tanhf(z);
        }
        int r = row0 + ty * 4 + u;
        *(float4*)&g_ea[r * 256 + col]     = make_float4(o[0], o[1], o[2], o[3]);
        *(float4*)&g_ea[r * 256 + col + 4] = make_float4(o[4], o[5], o[6], o[7]);
    }
}

// =====================================================================
// kf table (63 CTAs) + f_W(reads-half) transpose (8 CTAs); plain FMA
// =====================================================================
__global__ void k_kfT(const float* __restrict__ k_emb, const float* __restrict__ f_b,
                      const float* __restrict__ f_W) {
    __shared__ float Xs[32 * DIM];
    __shared__ __align__(16) float Ws[16 * 132];
    int bid = blockIdx.x;
    int tid = threadIdx.x;
    if (bid >= 63) {
        int base = (bid - 63) * 2048;
        #pragma unroll
        for (int j = 0; j < 8; j++) {
            int idx = base + j * 256 + tid;
            int k = idx >> 7, ii = idx & 127;
            g_fWat[idx] = f_W[ii * 256 + k];
        }
        return;
    }
    int row0 = bid * 32;
    for (int i = tid; i < 32 * DIM; i += 256) {
        int rr = i >> 7;
        Xs[i] = (row0 + rr < NUM_C) ? k_emb[row0 * DIM + i] : 0.f;
    }
    int tx = tid & 31, ty = tid >> 5;      // col = tx*4
    float acc[4][4];
    #pragma unroll
    for (int u = 0; u < 4; u++)
        #pragma unroll
        for (int v = 0; v < 4; v++) acc[u][v] = 0.f;
    for (int kc = 0; kc < DIM; kc += 16) {
        __syncthreads();
        for (int i = tid; i < 16 * DIM; i += 256) {
            int kk = i & 15, col = i >> 4;
            Ws[kk * 132 + col] = f_W[col * 256 + 128 + kc + kk];
        }
        __syncthreads();
        #pragma unroll
        for (int kk = 0; kk < 16; kk++) {
            float4 w0 = *(const float4*)&Ws[kk * 132 + tx * 4];
            #pragma unroll
            for (int u = 0; u < 4; u++) {
                float x = Xs[(ty * 4 + u) * DIM + kc + kk];
                acc[u][0] = fmaf(x, w0.x, acc[u][0]);
                acc[u][1] = fmaf(x, w0.y, acc[u][1]);
                acc[u][2] = fmaf(x, w0.z, acc[u][2]);
                acc[u][3] = fmaf(x, w0.w, acc[u][3]);
            }
        }
    }
    int col = tx * 4;
    float b0 = f_b[col], b1 = f_b[col + 1], b2 = f_b[col + 2], b3 = f_b[col + 3];
    #pragma unroll
    for (int u = 0; u < 4; u++) {
        int r = row0 + ty * 4 + u;
        if (r < NUM_C)
            *(float4*)&g_kf[r * DIM + col] =
                make_float4(acc[u][0] + b0, acc[u][1] + b1, acc[u][2] + b2, acc[u][3] + b3);
    }
}

// =====================================================================
// Scan (R9-proven, verbatim): 512 CTAs = 64 b x 8 d-slices of 16,
// 128 threads, 1 sync/step, depth-4 compile-time rotation.
// =====================================================================
__global__ __launch_bounds__(128) void k_scan(const int* __restrict__ skill,
                                              const int* __restrict__ answer,
                                              const float* __restrict__ Mv0) {
    __shared__ int s_sk[TT], s_x[TT];
    __shared__ __align__(16) float w_sh[4][MP];
    __shared__ __align__(16) float e_sh[4][16];
    __shared__ __align__(16) float a_sh[4][16];
    int b = blockIdx.x >> 3;
    int dbase = (blockIdx.x & 7) * 16;
    int tid = threadIdx.x;
    int wid = tid >> 5, lane = tid & 31;
    int mg = lane >> 2, dq = lane & 3;
    int dd = wid * 4 + dq;                 // 0..15 within slice

    for (int t = tid; t < TT; t += 128) {
        int s = skill[b * TT + t];
        int aa = answer[b * TT + t];
        if (aa > 1) aa = 1;
        s_sk[t] = s;
        s_x[t] = s + NUM_C * aa;
    }

    float mv[7];
    #pragma unroll
    for (int i = 0; i < 7; i++) {
        int m = mg * 7 + i;
        mv[i] = (m < MM) ? Mv0[m * DIM + dbase + dd] : 0.f;
    }
    __syncthreads();   // s_sk/s_x visible

    // gather roles: tid<56 -> w, [64,80) -> e, [80,96) -> a
    bool isW = tid < MP;
    bool isE = (tid >= 64) && (tid < 80);
    bool isA = (tid >= 80) && (tid < 96);
    bool lp = isW || isE || isA;
    int eoff = isE ? (dbase + (tid - 64)) : (128 + dbase + (tid - 80));

    float pfR[4];          // pfR[s&3] holds gathered value for step s
    pfR[0] = 0.f; pfR[1] = 0.f; pfR[2] = 0.f; pfR[3] = 0.f;
    if (lp) {
        float v0;
        if (isW) {
            v0      = g_w[s_sk[0] * MP + tid];
            pfR[1]  = g_w[s_sk[1] * MP + tid];
            pfR[2]  = g_w[s_sk[2] * MP + tid];
            pfR[3]  = g_w[s_sk[3] * MP + tid];
            w_sh[0][tid] = v0;
        } else {
            v0      = g_ea[s_x[0] * 256 + eoff];
            pfR[1]  = g_ea[s_x[1] * 256 + eoff];
            pfR[2]  = g_ea[s_x[2] * 256 + eoff];
            pfR[3]  = g_ea[s_x[3] * 256 + eoff];
            if (isE) e_sh[0][tid - 64] = v0;
            else     a_sh[0][tid - 80] = v0;
        }
    }
    __syncthreads();

    int outbase = (b * TT) * DIM + dbase + dd;

    for (int t0 = 0; t0 < TT; t0 += 4) {
        #pragma unroll
        for (int q = 0; q < 4; q++) {
            int t = t0 + q;
            // ---- compute step t from buffers[q] ----
            float e = e_sh[q][dd];
            float a = a_sh[q][dd];
            float acc = 0.f;
            #pragma unroll
            for (int i = 0; i < 7; i++) {
                float wm = w_sh[q][mg * 7 + i];
                acc = fmaf(wm, mv[i], acc);                      // PRE-update read
                mv[i] = fmaf(wm, fmaf(-e, mv[i], a), mv[i]);
            }
            acc += __shfl_xor_sync(~0u, acc, 4);
            acc += __shfl_xor_sync(~0u, acc, 8);
            acc += __shfl_xor_sync(~0u, acc, 16);
            if (mg == 0) g_reads[outbase + t * DIM] = acc;
            // ---- STS buffers for step t+1 (value loaded at t-3) ----
            if (lp && t + 1 < TT) {
                float pv = pfR[(q + 1) & 3];
                int nb = (q + 1) & 3;
                if (isW)      w_sh[nb][tid] = pv;
                else if (isE) e_sh[nb][tid - 64] = pv;
                else          a_sh[nb][tid - 80] = pv;
            }
            // ---- LDG gather for step t+4 into just-freed slot q ----
            if (lp && t + 4 < TT) {
                float nv;
                if (isW) nv = g_w[s_sk[t + 4] * MP + tid];
                else     nv = g_ea[s_x[t + 4] * 256 + eoff];
                pfR[q] = nv;
            }
            __syncthreads();
        }
    }
}

// =====================================================================
// fpred v2: 199 CTAs x 64 rows, 256 threads. FULL fWat resident in
// dynamic smem (64KB) + X tile (64x132, padded for float4), ZERO
// barriers in the GEMM mainloop, float4 LDS for X and W, k-blocked x4.
// =====================================================================
#define FP_XPITCH 132
#define FP_SMEM ((64 * FP_XPITCH + DIM * DIM) * 4)
__global__ __launch_bounds__(256) void k_fpred(const int* __restrict__ skill,
                                               const float* __restrict__ p_W,
                                               const float* __restrict__ p_b,
                                               float* __restrict__ out) {
    extern __shared__ __align__(16) float dsm[];
    float* Xs = dsm;                     // [64][132]
    float* Ws = dsm + 64 * FP_XPITCH;    // [128][128] full fWat
    __shared__ int s_kf[64], s_nx[64];
    int row0 = blockIdx.x * 64;
    int tid = threadIdx.x;

    if (tid < 64) {
        int r = row0 + tid;
        int bb = r / 199;
        int t = r - bb * 199;
        s_kf[tid] = skill[bb * TT + t];
        s_nx[tid] = skill[bb * TT + t + 1];
    }
    // load full weights: coalesced float4
    for (int i = tid * 4; i < DIM * DIM; i += 1024)
        *(float4*)&Ws[i] = *(const float4*)&g_fWat[i];
    // load X tile: each group of 4 threads handles one row
    {
        int row = tid >> 2, qr = tid & 3;
        int r = row0 + row;
        int bb = r / 199;
        int t = r - bb * 199;
        const float* src = &g_reads[(bb * TT + t) * DIM];
        #pragma unroll
        for (int j = 0; j < 8; j++) {
            int c4 = (qr + j * 4) * 4;     // float index, 16B aligned
            *(float4*)&Xs[row * FP_XPITCH + c4] = *(const float4*)&src[c4];
        }
    }
    __syncthreads();

    int tx = tid & 15, ty = tid >> 4;    // cols tx*8.., rows ty*4..
    float acc[4][8];
    #pragma unroll
    for (int u = 0; u < 4; u++)
        #pragma unroll
        for (int v = 0; v < 8; v++) acc[u][v] = 0.f;

    #pragma unroll 4
    for (int k = 0; k < DIM; k += 4) {
        float4 x0 = *(const float4*)&Xs[(ty * 4 + 0) * FP_XPITCH + k];
        float4 x1 = *(const float4*)&Xs[(ty * 4 + 1) * FP_XPITCH + k];
        float4 x2 = *(const float4*)&Xs[(ty * 4 + 2) * FP_XPITCH + k];
        float4 x3 = *(const float4*)&Xs[(ty * 4 + 3) * FP_XPITCH + k];
        #pragma unroll
        for (int kk = 0; kk < 4; kk++) {
            float4 w0 = *(const float4*)&Ws[(k + kk) * DIM + tx * 8];
            float4 w1 = *(const float4*)&Ws[(k + kk) * DIM + tx * 8 + 4];
            float xv[4];
            xv[0] = (kk == 0) ? x0.x : (kk == 1) ? x0.y : (kk == 2) ? x0.z : x0.w;
            xv[1] = (kk == 0) ? x1.x : (kk == 1) ? x1.y : (kk == 2) ? x1.z : x1.w;
            xv[2] = (kk == 0) ? x2.x : (kk == 1) ? x2.y : (kk == 2) ? x2.z : x2.w;
            xv[3] = (kk == 0) ? x3.x : (kk == 1) ? x3.y : (kk == 2) ? x3.z : x3.w;
            #pragma unroll
            for (int u = 0; u < 4; u++) {
                acc[u][0] = fmaf(xv[u], w0.x, acc[u][0]);
                acc[u][1] = fmaf(xv[u], w0.y, acc[u][1]);
                acc[u][2] = fmaf(xv[u], w0.z, acc[u][2]);
                acc[u][3] = fmaf(xv[u], w0.w, acc[u][3]);
                acc[u][4] = fmaf(xv[u], w1.x, acc[u][4]);
                acc[u][5] = fmaf(xv[u], w1.y, acc[u][5]);
                acc[u][6] = fmaf(xv[u], w1.z, acc[u][6]);
                acc[u][7] = fmaf(xv[u], w1.w, acc[u][7]);
            }
        }
    }
    __syncthreads();   // all Xs reads done -> overwrite with f

    int col = tx * 8;
    #pragma unroll
    for (int u = 0; u < 4; u++) {
        int row = ty * 4 + u;
        int sc = s_kf[row];
        float4 k0 = *(const float4*)&g_kf[sc * DIM + col];
        float4 k1 = *(const float4*)&g_kf[sc * DIM + col + 4];
        Xs[row * FP_XPITCH + col + 0] = tanhf(acc[u][0] + k0.x);
        Xs[row * FP_XPITCH + col + 1] = tanhf(acc[u][1] + k0.y);
        Xs[row * FP_XPITCH + col + 2] = tanhf(acc[u][2] + k0.z);
        Xs[row * FP_XPITCH + col + 3] = tanhf(acc[u][3] + k0.w);
        Xs[row * FP_XPITCH + col + 4] = tanhf(acc[u][4] + k1.x);
        Xs[row * FP_XPITCH + col + 5] = tanhf(acc[u][5] + k1.y);
        Xs[row * FP_XPITCH + col + 6] = tanhf(acc[u][6] + k1.z);
        Xs[row * FP_XPITCH + col + 7] = tanhf(acc[u][7] + k1.w);
    }
    __syncthreads();

    int wid = tid >> 5, lane = tid & 31;
    for (int rr = wid * 8; rr < wid * 8 + 8; rr++) {
        int ns = s_nx[rr];
        int idx = (ns < NUM_C) ? ns : (NUM_C - 1);
        const float* pw = p_W + idx * DIM;
        float a = 0.f;
        #pragma unroll
        for (int q = 0; q < 4; q++)
            a = fmaf(Xs[rr * FP_XPITCH + lane + 32 * q], pw[lane + 32 * q], a);
        #pragma unroll
        for (int off = 16; off; off >>= 1) a += __shfl_xor_sync(~0u, a, off);
        if (lane == 0) {
            float pr = sigmoidf_(a + p_b[idx]);
            out[row0 + rr] = (ns < NUM_C) ? pr : 0.f;
        }
    }
}

// ---------------- launch: forked-capture stream graph ----------------------
extern "C" void kernel_launch(void* const* d_in, const int* in_sizes, int n_in,
                              void* d_out, int out_size) {
    const int*   skill  = (const int*)d_in[0];
    const int*   answer = (const int*)d_in[1];
    const float* k_emb  = (const float*)d_in[2];
    const float* v_emb  = (const float*)d_in[3];
    const float* Mk     = (const float*)d_in[4];
    const float* Mv0    = (const float*)d_in[5];
    const float* f_W    = (const float*)d_in[6];
    const float* f_b    = (const float*)d_in[7];
    const float* p_W    = (const float*)d_in[8];
    const float* p_b    = (const float*)d_in[9];
    const float* e_W    = (const float*)d_in[10];
    const float* e_b    = (const float*)d_in[11];
    const float* a_W    = (const float*)d_in[12];
    const float* a_b    = (const float*)d_in[13];
    float* out = (float*)d_out;

    static cudaStream_t sA = nullptr, sB = nullptr, sC = nullptr;
    static cudaEvent_t evR = nullptr, evA = nullptr, evB = nullptr, evC = nullptr;
    if (!sA) {   // first call = correctness run (not captured): safe to create
        cudaStreamCreateWithFlags(&sA, cudaStreamNonBlocking);
        cudaStreamCreateWithFlags(&sB, cudaStreamNonBlocking);
        cudaStreamCreateWithFlags(&sC, cudaStreamNonBlocking);
        cudaEventCreateWithFlags(&evR, cudaEventDisableTiming);
        cudaEventCreateWithFlags(&evA, cudaEventDisableTiming);
        cudaEventCreateWithFlags(&evB, cudaEventDisableTiming);
        cudaEventCreateWithFlags(&evC, cudaEventDisableTiming);
        cudaFuncSetAttribute(k_fpred, cudaFuncAttributeMaxDynamicSharedMemorySize, FP_SMEM);
    }

    cudaEventRecord(evR, 0);
    cudaStreamWaitEvent(sA, evR, 0);
    cudaStreamWaitEvent(sB, evR, 0);
    cudaStreamWaitEvent(sC, evR, 0);

    k_wtable<<<125, 256, 0, sA>>>(k_emb, Mk);
    k_ea    <<<125, 256, 0, sB>>>(v_emb, e_b, a_b, e_W, a_W);
    k_kfT   <<<71, 256, 0, sC>>>(k_emb, f_b, f_W);      // overlaps scan

    cudaEventRecord(evA, sA);
    cudaEventRecord(evB, sB);
    cudaEventRecord(evC, sC);

    cudaStreamWaitEvent(0, evA, 0);
    cudaStreamWaitEvent(0, evB, 0);
    k_scan<<<512, 128>>>(skill, answer, Mv0);

    cudaStreamWaitEvent(0, evC, 0);
    k_fpred<<<199, 256, FP_SMEM>>>(skill, p_W, p_b, out);
}